// round 2
// baseline (speedup 1.0000x reference)
#include <cuda_runtime.h>
#include <cstdint>

#define DINLINE __device__ __forceinline__

// ---------------- problem sizes ----------------
#define B_  64
#define TN_ 131072
#define TE_ 262144
#define QD_ 768
#define PD_ 512
#define KD_ 512

// ---------------- device scratch ----------------
__device__ float g_qn[B_ * PD_];
__device__ float g_qe[B_ * PD_];
__device__ float g_wtn[PD_ * KD_];   // W_n transposed: [P][K], tf32-rounded
__device__ float g_wte[PD_ * KD_];
__device__ float g_sn[TN_];
__device__ float g_se[TE_];
__device__ float g_max[128];         // encoded-uint monotonic floats; 0..63 nodes, 64..127 edges
__device__ float g_sum[128];

// ---------------- helpers ----------------
DINLINE float to_tf32(float x) {
    float y;
    asm("cvt.rna.tf32.f32 %0, %1;" : "=f"(y) : "f"(x));
    return y;
}

// monotonic float<->uint encoding for atomicMax on floats
DINLINE unsigned fenc(float x) {
    unsigned u = __float_as_uint(x);
    return (u & 0x80000000u) ? ~u : (u | 0x80000000u);
}
DINLINE float fdec(unsigned e) {
    return (e & 0x80000000u) ? __uint_as_float(e ^ 0x80000000u)
                             : __uint_as_float(~e);
}

DINLINE void cp16(uint32_t s, const void* g) {
    asm volatile("cp.async.cg.shared.global [%0], [%1], 16;"
                 :: "r"(s), "l"(g) : "memory");
}
DINLINE void cp_commit() { asm volatile("cp.async.commit_group;" ::: "memory"); }
template<int N> DINLINE void cp_wait() {
    asm volatile("cp.async.wait_group %0;" :: "n"(N) : "memory");
}

DINLINE uint32_t smem_u32(const void* p) {
    uint32_t a;
    asm("{ .reg .u64 t; cvta.to.shared.u64 t, %1; cvt.u32.u64 %0, t; }"
        : "=r"(a) : "l"(p));
    return a;
}

DINLINE void mma_tf32(float* c, const uint32_t* a, const uint32_t* b) {
    asm volatile(
        "mma.sync.aligned.m16n8k8.row.col.f32.tf32.tf32.f32 "
        "{%0,%1,%2,%3}, {%4,%5,%6,%7}, {%8,%9}, {%0,%1,%2,%3};"
        : "+f"(c[0]), "+f"(c[1]), "+f"(c[2]), "+f"(c[3])
        : "r"(a[0]), "r"(a[1]), "r"(a[2]), "r"(a[3]),
          "r"(b[0]), "r"(b[1]));
}

// ---------------- main fused GEMM ----------------
// Tile: M=128 (blockIdx.y), N=128 (blockIdx.x of 4), K=512 in 16 chunks of 32.
// SMEM per stage: A 128x32 (stride 36), B 128x32 (stride 36). 2 stages.
#define KCH   32
#define ASTR  36
#define TILEF (128 * ASTR)          // floats per tile
#define STAGEF (2 * TILEF)          // A + B
#define SMEM_FLOATS (2 * STAGEF + 128)
#define SMEM_BYTES  (SMEM_FLOATS * 4)

__global__ void __launch_bounds__(256, 2) k_main(
    const float* __restrict__ A, const int* __restrict__ gid,
    const float* __restrict__ Wt, const float* __restrict__ qeff,
    const float* __restrict__ wv, float* __restrict__ sOut)
{
    extern __shared__ float smem[];
    float* s_sm = smem + 2 * STAGEF;

    const int tid  = threadIdx.x;
    const int lane = tid & 31;
    const int warp = tid >> 5;
    const int wm   = warp & 3;   // 0..3 -> M block of 32
    const int wn   = warp >> 2;  // 0..1 -> N block of 64

    const int mBase = blockIdx.y * 128;
    const int nBase = blockIdx.x * 128;

    const uint32_t sb = smem_u32(smem);

    if (tid < 128) s_sm[tid] = 0.f;

    // cp.async loader for one 32-k chunk into stage buf
    const int ldRow = tid >> 3;        // 0..31 step of rows per iter (4 iters x 32 rows)
    const int ldF4  = tid & 7;         // which 16B of the 128B row-chunk
    auto load_chunk = [&](int buf, int kc) {
        const uint32_t aBase = sb + (buf * STAGEF) * 4;
        const uint32_t bBase = sb + (buf * STAGEF + TILEF) * 4;
        const float* Ac = A  + (size_t)mBase * KD_ + kc * KCH + ldF4 * 4;
        const float* Bc = Wt + (size_t)nBase * KD_ + kc * KCH + ldF4 * 4;
#pragma unroll
        for (int it = 0; it < 4; ++it) {
            int row = it * 32 + ldRow;
            cp16(aBase + (row * ASTR + ldF4 * 4) * 4, Ac + (size_t)row * KD_);
            cp16(bBase + (row * ASTR + ldF4 * 4) * 4, Bc + (size_t)row * KD_);
        }
        cp_commit();
    };

    float c[2][8][4];
#pragma unroll
    for (int mt = 0; mt < 2; ++mt)
#pragma unroll
        for (int nt = 0; nt < 8; ++nt)
#pragma unroll
            for (int i = 0; i < 4; ++i) c[mt][nt][i] = 0.f;

    load_chunk(0, 0);

    const int rA = wm * 32 + (lane >> 2);
    const int rB = wn * 64 + (lane >> 2);
    const int kq = lane & 3;

#pragma unroll 1
    for (int kc = 0; kc < 16; ++kc) {
        const int buf = kc & 1;
        if (kc + 1 < 16) load_chunk(buf ^ 1, kc + 1);
        if (kc + 1 < 16) cp_wait<1>(); else cp_wait<0>();
        __syncthreads();

        const uint32_t* As = reinterpret_cast<const uint32_t*>(smem + buf * STAGEF);
        const uint32_t* Bs = reinterpret_cast<const uint32_t*>(smem + buf * STAGEF + TILEF);

#pragma unroll
        for (int ks = 0; ks < 4; ++ks) {
            const int kof = ks * 8 + kq;
            uint32_t a[2][4];
#pragma unroll
            for (int mt = 0; mt < 2; ++mt) {
                const int r = rA + mt * 16;
                a[mt][0] = As[r * ASTR + kof];
                a[mt][1] = As[(r + 8) * ASTR + kof];
                a[mt][2] = As[r * ASTR + kof + 4];
                a[mt][3] = As[(r + 8) * ASTR + kof + 4];
            }
            uint32_t b[8][2];
#pragma unroll
            for (int nt = 0; nt < 8; ++nt) {
                const int n = rB + nt * 8;
                b[nt][0] = Bs[n * ASTR + kof];
                b[nt][1] = Bs[n * ASTR + kof + 4];
            }
#pragma unroll
            for (int mt = 0; mt < 2; ++mt)
#pragma unroll
                for (int nt = 0; nt < 8; ++nt)
                    mma_tf32(c[mt][nt], a[mt], b[nt]);
        }
        __syncthreads();
    }

    // ---- epilogue: s[m] += sum_n tanh(D + qeff[gid[m]][n]) * wv[n] ----
    const int n0 = wn * 64 + 2 * (lane & 3);
#pragma unroll
    for (int mt = 0; mt < 2; ++mt) {
#pragma unroll
        for (int h = 0; h < 2; ++h) {
            const int row = wm * 32 + mt * 16 + (lane >> 2) + h * 8;
            const int g = __ldg(gid + mBase + row);
            const float* qrow = qeff + (size_t)g * PD_ + nBase;
            float s = 0.f;
#pragma unroll
            for (int nt = 0; nt < 8; ++nt) {
                const int nn = n0 + nt * 8;
                float2 q2 = *reinterpret_cast<const float2*>(qrow + nn);
                float2 w2 = *reinterpret_cast<const float2*>(wv + nBase + nn);
                float x0 = tanhf(c[mt][nt][h * 2 + 0] + q2.x);
                float x1 = tanhf(c[mt][nt][h * 2 + 1] + q2.y);
                s = fmaf(x0, w2.x, s);
                s = fmaf(x1, w2.y, s);
            }
            s += __shfl_xor_sync(0xffffffffu, s, 1);
            s += __shfl_xor_sync(0xffffffffu, s, 2);
            if ((lane & 3) == 0) atomicAdd(&s_sm[row], s);
        }
    }
    __syncthreads();
    if (tid < 128) atomicAdd(&sOut[mBase + tid], s_sm[tid]);
}

// ---------------- small kernels ----------------
__global__ void k_zero(float* sn, float* se, float* gmax, float* gsum) {
    int i = blockIdx.x * blockDim.x + threadIdx.x;
    if (i < TN_) sn[i] = 0.f;
    if (i < TE_) se[i] = 0.f;
    if (i < 128) { reinterpret_cast<unsigned*>(gmax)[i] = 0u; gsum[i] = 0.f; }
}

// Wt[p][k] = round_tf32(W[k][p])  (512x512)
__global__ void k_transpose(const float* __restrict__ W, float* __restrict__ Wt) {
    __shared__ float tile[32][33];
    int x = blockIdx.x * 32 + threadIdx.x;   // p
    int y = blockIdx.y * 32 + threadIdx.y;   // k
#pragma unroll
    for (int j = 0; j < 32; j += 8)
        tile[threadIdx.y + j][threadIdx.x] = W[(y + j) * 512 + x];
    __syncthreads();
    int xo = blockIdx.y * 32 + threadIdx.x;  // k
    int yo = blockIdx.x * 32 + threadIdx.y;  // p
#pragma unroll
    for (int j = 0; j < 32; j += 8)
        Wt[(yo + j) * 512 + xo] = to_tf32(tile[threadIdx.x][threadIdx.y + j]);
}

// qeff[b][p] = question[b,:] @ Wq[:,p] + bq[p] + bh[p]
__global__ void k_qproj(const float* __restrict__ q, const float* __restrict__ Wq,
                        const float* __restrict__ bq, const float* __restrict__ bh,
                        float* __restrict__ out) {
    int idx = blockIdx.x * blockDim.x + threadIdx.x;   // 0..32767
    int b = idx >> 9, p = idx & 511;
    const float* qr = q + b * QD_;
    float acc = 0.f;
#pragma unroll 4
    for (int k = 0; k < QD_; k++)
        acc = fmaf(__ldg(qr + k), __ldg(Wq + k * 512 + p), acc);
    out[idx] = acc + __ldg(bq + p) + __ldg(bh + p);
}

__global__ void k_max(const float* __restrict__ s, const int* __restrict__ gid,
                      float* __restrict__ gmax, int n) {
    __shared__ unsigned sm[64];
    int t = threadIdx.x;
    if (t < 64) sm[t] = 0u;
    __syncthreads();
    int i = blockIdx.x * blockDim.x + t;
    if (i < n) atomicMax(&sm[__ldg(gid + i)], fenc(__ldg(s + i)));
    __syncthreads();
    if (t < 64 && sm[t] != 0u)
        atomicMax(reinterpret_cast<unsigned*>(gmax) + t, sm[t]);
}

__global__ void k_sumexp(const float* __restrict__ s, const int* __restrict__ gid,
                         const float* __restrict__ gmax, float* __restrict__ gsum, int n) {
    __shared__ float ssum[64];
    int t = threadIdx.x;
    if (t < 64) ssum[t] = 0.f;
    __syncthreads();
    int i = blockIdx.x * blockDim.x + t;
    if (i < n) {
        int g = __ldg(gid + i);
        float m = fdec(reinterpret_cast<const unsigned*>(gmax)[g]);
        atomicAdd(&ssum[g], expf(__ldg(s + i) - m));
    }
    __syncthreads();
    if (t < 64 && ssum[t] != 0.f) atomicAdd(&gsum[t], ssum[t]);
}

__global__ void k_norm(const float* __restrict__ s, const int* __restrict__ gid,
                       const float* __restrict__ gmax, const float* __restrict__ gsum,
                       float* __restrict__ out, int n) {
    int i = blockIdx.x * blockDim.x + threadIdx.x;
    if (i < n) {
        int g = __ldg(gid + i);
        float m = fdec(reinterpret_cast<const unsigned*>(gmax)[g]);
        out[i] = expf(__ldg(s + i) - m) / __ldg(gsum + g);
    }
}

// ---------------- launch ----------------
extern "C" void kernel_launch(void* const* d_in, const int* in_sizes, int n_in,
                              void* d_out, int out_size) {
    const float* question = (const float*)d_in[0];
    const float* nodes    = (const float*)d_in[1];
    const float* edges    = (const float*)d_in[2];
    const float* W_nq     = (const float*)d_in[3];
    const float* b_nq     = (const float*)d_in[4];
    const float* W_n      = (const float*)d_in[5];
    const float* b_n      = (const float*)d_in[6];
    const float* w_nv     = (const float*)d_in[7];
    // d_in[8] = b_nv (scalar) — softmax is shift-invariant, unused
    const float* W_eq     = (const float*)d_in[9];
    const float* b_eq     = (const float*)d_in[10];
    const float* W_e      = (const float*)d_in[11];
    const float* b_e      = (const float*)d_in[12];
    const float* w_ev     = (const float*)d_in[13];
    // d_in[14] = b_ev — unused
    const int* node_gid   = (const int*)d_in[15];
    const int* edge_gid   = (const int*)d_in[16];
    float* out = (float*)d_out;

    float *qn, *qe, *wtn, *wte, *sn, *se, *mx, *sm;
    cudaGetSymbolAddress((void**)&qn,  g_qn);
    cudaGetSymbolAddress((void**)&qe,  g_qe);
    cudaGetSymbolAddress((void**)&wtn, g_wtn);
    cudaGetSymbolAddress((void**)&wte, g_wte);
    cudaGetSymbolAddress((void**)&sn,  g_sn);
    cudaGetSymbolAddress((void**)&se,  g_se);
    cudaGetSymbolAddress((void**)&mx,  g_max);
    cudaGetSymbolAddress((void**)&sm,  g_sum);

    cudaFuncSetAttribute(k_main, cudaFuncAttributeMaxDynamicSharedMemorySize, SMEM_BYTES);

    k_zero<<<TE_ / 512, 512>>>(sn, se, mx, sm);
    k_transpose<<<dim3(16, 16), dim3(32, 8)>>>(W_n, wtn);
    k_transpose<<<dim3(16, 16), dim3(32, 8)>>>(W_e, wte);
    k_qproj<<<128, 256>>>(question, W_nq, b_nq, b_n, qn);
    k_qproj<<<128, 256>>>(question, W_eq, b_eq, b_e, qe);

    k_main<<<dim3(4, TN_ / 128), 256, SMEM_BYTES>>>(nodes, node_gid, wtn, qn, w_nv, sn);
    k_main<<<dim3(4, TE_ / 128), 256, SMEM_BYTES>>>(edges, edge_gid, wte, qe, w_ev, se);

    k_max<<<TN_ / 256, 256>>>(sn, node_gid, mx,      TN_);
    k_max<<<TE_ / 256, 256>>>(se, edge_gid, mx + 64, TE_);
    k_sumexp<<<TN_ / 256, 256>>>(sn, node_gid, mx,      sm,      TN_);
    k_sumexp<<<TE_ / 256, 256>>>(se, edge_gid, mx + 64, sm + 64, TE_);
    k_norm<<<TN_ / 256, 256>>>(sn, node_gid, mx,      sm,      out,       TN_);
    k_norm<<<TE_ / 256, 256>>>(se, edge_gid, mx + 64, sm + 64, out + TN_, TE_);
}

// round 3
// speedup vs baseline: 1.4868x; 1.4868x over previous
#include <cuda_runtime.h>
#include <cuda_bf16.h>
#include <cstdint>

#define DINLINE __device__ __forceinline__

// ---------------- problem sizes ----------------
#define B_  64
#define TN_ 131072
#define TE_ 262144
#define QD_ 768
#define PD_ 512
#define KD_ 512

// ---------------- device scratch ----------------
__device__ float g_qn[B_ * PD_];
__device__ float g_qe[B_ * PD_];
__device__ __nv_bfloat16 g_wtn[PD_ * KD_];   // W_n transposed [P][K], bf16
__device__ __nv_bfloat16 g_wte[PD_ * KD_];
__device__ float g_sn[TN_];
__device__ float g_se[TE_];
__device__ float g_max[128];   // encoded-uint monotonic floats; 0..63 nodes, 64..127 edges
__device__ float g_sum[128];

// ---------------- helpers ----------------
// monotonic float<->uint encoding for atomicMax on floats
DINLINE unsigned fenc(float x) {
    unsigned u = __float_as_uint(x);
    return (u & 0x80000000u) ? ~u : (u | 0x80000000u);
}
DINLINE float fdec(unsigned e) {
    return (e & 0x80000000u) ? __uint_as_float(e ^ 0x80000000u)
                             : __uint_as_float(~e);
}

DINLINE void cp16(uint32_t s, const void* g) {
    asm volatile("cp.async.cg.shared.global [%0], [%1], 16;"
                 :: "r"(s), "l"(g) : "memory");
}
DINLINE void cp_commit() { asm volatile("cp.async.commit_group;" ::: "memory"); }
template<int N> DINLINE void cp_wait() {
    asm volatile("cp.async.wait_group %0;" :: "n"(N) : "memory");
}

DINLINE uint32_t smem_u32(const void* p) {
    uint32_t a;
    asm("{ .reg .u64 t; cvta.to.shared.u64 t, %1; cvt.u32.u64 %0, t; }"
        : "=r"(a) : "l"(p));
    return a;
}

DINLINE void mma_bf16(float* c, const uint32_t* a, const uint32_t* b) {
    asm volatile(
        "mma.sync.aligned.m16n8k16.row.col.f32.bf16.bf16.f32 "
        "{%0,%1,%2,%3}, {%4,%5,%6,%7}, {%8,%9}, {%0,%1,%2,%3};"
        : "+f"(c[0]), "+f"(c[1]), "+f"(c[2]), "+f"(c[3])
        : "r"(a[0]), "r"(a[1]), "r"(a[2]), "r"(a[3]),
          "r"(b[0]), "r"(b[1]));
}

DINLINE uint32_t pack_bf16x2(float lo, float hi) {
    __nv_bfloat162 v = __float22bfloat162_rn(make_float2(lo, hi));
    return *reinterpret_cast<uint32_t*>(&v);
}

// ---------------- main fused GEMM ----------------
// Tile: M=128 (blockIdx.y), N=128 (blockIdx.x in 0..3), K=512 in 16 chunks of 32.
// SMEM (bf16, 80B padded rows for conflict-free fragment loads):
//   A0 @ 0      (128 x 80B = 10240)
//   A1 @ 10240
//   B0 @ 20480
//   B1 @ 30720
//   s_sm @ 40960 (128 floats)
#define ROWB  80u
#define TILEB 10240u
#define SM_OFF 40960u
#define SMEM_BYTES (40960 + 512)

__global__ void __launch_bounds__(256, 2) k_main(
    const float* __restrict__ A, const int* __restrict__ gid,
    const __nv_bfloat16* __restrict__ Wt, const float* __restrict__ qeff,
    const float* __restrict__ wv, float* __restrict__ sOut)
{
    extern __shared__ char smem[];
    float* s_sm = reinterpret_cast<float*>(smem + SM_OFF);

    const int tid  = threadIdx.x;
    const int lane = tid & 31;
    const int warp = tid >> 5;
    const int wm   = warp & 3;   // M block of 32
    const int wn   = warp >> 2;  // N block of 64

    const int mBase = blockIdx.y * 128;
    const int nBase = blockIdx.x * 128;

    const uint32_t sb = smem_u32(smem);

    if (tid < 128) s_sm[tid] = 0.f;

    // ---- loaders ----
    // A: 128 rows x 32 f32 per chunk; each thread: 4 float4 (rows t>>3 + i*32, quad t&7)
    const int aRow = tid >> 3;
    const int aQ   = tid & 7;
    const float* Abase = A + (size_t)(mBase + aRow) * KD_ + aQ * 4;

    auto ldA = [&](float4* ra, int kc) {
        const float* p = Abase + kc * 32;
#pragma unroll
        for (int i = 0; i < 4; ++i)
            ra[i] = *reinterpret_cast<const float4*>(p + (size_t)i * 32 * KD_);
    };
    auto stsA = [&](const float4* ra, int buf) {
        const uint32_t base = sb + buf * TILEB + aRow * ROWB + aQ * 8;
#pragma unroll
        for (int i = 0; i < 4; ++i) {
            uint32_t lo = pack_bf16x2(ra[i].x, ra[i].y);
            uint32_t hi = pack_bf16x2(ra[i].z, ra[i].w);
            asm volatile("st.shared.v2.b32 [%0], {%1,%2};"
                         :: "r"(base + i * 32 * ROWB), "r"(lo), "r"(hi) : "memory");
        }
    };
    // B: 128 n-rows x 32 bf16 per chunk = 8KB = 512 x 16B; thread does 2
    const int bIdx0 = tid * 2;
    auto cpB = [&](int buf, int kc) {
#pragma unroll
        for (int j = 0; j < 2; ++j) {
            int idx = bIdx0 + j;
            int n = idx >> 2, g = idx & 3;
            cp16(sb + 20480u + buf * TILEB + n * ROWB + g * 16,
                 Wt + (size_t)(nBase + n) * KD_ + kc * 32 + g * 8);
        }
        cp_commit();
    };

    float c[2][8][4];
#pragma unroll
    for (int mt = 0; mt < 2; ++mt)
#pragma unroll
        for (int nt = 0; nt < 8; ++nt)
#pragma unroll
            for (int i = 0; i < 4; ++i) c[mt][nt][i] = 0.f;

    float4 ra[4];
    ldA(ra, 0);
    cpB(0, 0);

    // fragment addresses (byte offsets within a tile)
    const uint32_t aFragOff = (wm * 32 + (lane >> 2)) * ROWB + (lane & 3) * 4;
    const uint32_t bFragOff = (wn * 64 + (lane >> 2)) * ROWB + (lane & 3) * 4;

#pragma unroll 1
    for (int kc = 0; kc < 16; ++kc) {
        const int buf = kc & 1;
        stsA(ra, buf);
        if (kc + 1 < 16) {
            ldA(ra, kc + 1);
            cpB(buf ^ 1, kc + 1);
            cp_wait<1>();
        } else {
            cp_wait<0>();
        }
        __syncthreads();

        const uint32_t aT = sb + buf * TILEB + aFragOff;
        const uint32_t bT = sb + 20480u + buf * TILEB + bFragOff;

#pragma unroll
        for (int ks = 0; ks < 2; ++ks) {
            const uint32_t ko = ks * 32;
            uint32_t a[2][4];
#pragma unroll
            for (int mt = 0; mt < 2; ++mt) {
                const uint32_t r = aT + mt * 16 * ROWB + ko;
                asm volatile("ld.shared.b32 %0, [%1];" : "=r"(a[mt][0]) : "r"(r));
                asm volatile("ld.shared.b32 %0, [%1];" : "=r"(a[mt][1]) : "r"(r + 8 * ROWB));
                asm volatile("ld.shared.b32 %0, [%1];" : "=r"(a[mt][2]) : "r"(r + 16));
                asm volatile("ld.shared.b32 %0, [%1];" : "=r"(a[mt][3]) : "r"(r + 8 * ROWB + 16));
            }
            uint32_t b[8][2];
#pragma unroll
            for (int nt = 0; nt < 8; ++nt) {
                const uint32_t nb = bT + nt * 8 * ROWB + ko;
                asm volatile("ld.shared.b32 %0, [%1];" : "=r"(b[nt][0]) : "r"(nb));
                asm volatile("ld.shared.b32 %0, [%1];" : "=r"(b[nt][1]) : "r"(nb + 16));
            }
#pragma unroll
            for (int mt = 0; mt < 2; ++mt)
#pragma unroll
                for (int nt = 0; nt < 8; ++nt)
                    mma_bf16(c[mt][nt], a[mt], b[nt]);
        }
        __syncthreads();
    }

    // ---- epilogue: s[m] += sum_n tanh(D + qeff[gid[m]][n]) * wv[n] ----
    const int n0 = wn * 64 + 2 * (lane & 3);
#pragma unroll
    for (int mt = 0; mt < 2; ++mt) {
#pragma unroll
        for (int h = 0; h < 2; ++h) {
            const int row = wm * 32 + mt * 16 + (lane >> 2) + h * 8;
            const int g = __ldg(gid + mBase + row);
            const float* qrow = qeff + (size_t)g * PD_ + nBase;
            float s = 0.f;
#pragma unroll
            for (int nt = 0; nt < 8; ++nt) {
                const int nn = n0 + nt * 8;
                float2 q2 = *reinterpret_cast<const float2*>(qrow + nn);
                float2 w2 = *reinterpret_cast<const float2*>(wv + nBase + nn);
                float x0 = tanhf(c[mt][nt][h * 2 + 0] + q2.x);
                float x1 = tanhf(c[mt][nt][h * 2 + 1] + q2.y);
                s = fmaf(x0, w2.x, s);
                s = fmaf(x1, w2.y, s);
            }
            s += __shfl_xor_sync(0xffffffffu, s, 1);
            s += __shfl_xor_sync(0xffffffffu, s, 2);
            if ((lane & 3) == 0) atomicAdd(&s_sm[row], s);
        }
    }
    __syncthreads();
    if (tid < 128) atomicAdd(&sOut[mBase + tid], s_sm[tid]);
}

// ---------------- small kernels ----------------
__global__ void k_zero(float* sn, float* se, float* gmax, float* gsum) {
    int i = blockIdx.x * blockDim.x + threadIdx.x;
    if (i < TN_) sn[i] = 0.f;
    if (i < TE_) se[i] = 0.f;
    if (i < 128) { reinterpret_cast<unsigned*>(gmax)[i] = 0u; gsum[i] = 0.f; }
}

// Wt[p][k] = bf16(W[k][p])  (512x512)
__global__ void k_transpose(const float* __restrict__ W, __nv_bfloat16* __restrict__ Wt) {
    __shared__ float tile[32][33];
    int x = blockIdx.x * 32 + threadIdx.x;   // p
    int y = blockIdx.y * 32 + threadIdx.y;   // k
#pragma unroll
    for (int j = 0; j < 32; j += 8)
        tile[threadIdx.y + j][threadIdx.x] = W[(y + j) * 512 + x];
    __syncthreads();
    int xo = blockIdx.y * 32 + threadIdx.x;  // k
    int yo = blockIdx.x * 32 + threadIdx.y;  // p
#pragma unroll
    for (int j = 0; j < 32; j += 8)
        Wt[(yo + j) * 512 + xo] = __float2bfloat16(tile[threadIdx.x][threadIdx.y + j]);
}

// qeff[b][p] = question[b,:] @ Wq[:,p] + bq[p] + bh[p]; one block per b
__global__ void __launch_bounds__(512) k_qproj(
    const float* __restrict__ q, const float* __restrict__ Wq,
    const float* __restrict__ bq, const float* __restrict__ bh,
    float* __restrict__ out) {
    __shared__ float qs[QD_];
    const int b = blockIdx.x, p = threadIdx.x;
    for (int i = p; i < QD_; i += 512) qs[i] = q[b * QD_ + i];
    __syncthreads();
    float acc = 0.f;
#pragma unroll 8
    for (int k = 0; k < QD_; ++k)
        acc = fmaf(qs[k], __ldg(Wq + (size_t)k * 512 + p), acc);
    out[b * 512 + p] = acc + __ldg(bq + p) + __ldg(bh + p);
}

__global__ void k_max(const float* __restrict__ s, const int* __restrict__ gid,
                      float* __restrict__ gmax, int n) {
    __shared__ unsigned sm[64];
    int t = threadIdx.x;
    if (t < 64) sm[t] = 0u;
    __syncthreads();
    int i = blockIdx.x * blockDim.x + t;
    if (i < n) atomicMax(&sm[__ldg(gid + i)], fenc(__ldg(s + i)));
    __syncthreads();
    if (t < 64 && sm[t] != 0u)
        atomicMax(reinterpret_cast<unsigned*>(gmax) + t, sm[t]);
}

__global__ void k_sumexp(const float* __restrict__ s, const int* __restrict__ gid,
                         const float* __restrict__ gmax, float* __restrict__ gsum, int n) {
    __shared__ float ssum[64];
    int t = threadIdx.x;
    if (t < 64) ssum[t] = 0.f;
    __syncthreads();
    int i = blockIdx.x * blockDim.x + t;
    if (i < n) {
        int g = __ldg(gid + i);
        float m = fdec(reinterpret_cast<const unsigned*>(gmax)[g]);
        atomicAdd(&ssum[g], expf(__ldg(s + i) - m));
    }
    __syncthreads();
    if (t < 64 && ssum[t] != 0.f) atomicAdd(&gsum[t], ssum[t]);
}

__global__ void k_norm(const float* __restrict__ s, const int* __restrict__ gid,
                       const float* __restrict__ gmax, const float* __restrict__ gsum,
                       float* __restrict__ out, int n) {
    int i = blockIdx.x * blockDim.x + threadIdx.x;
    if (i < n) {
        int g = __ldg(gid + i);
        float m = fdec(reinterpret_cast<const unsigned*>(gmax)[g]);
        out[i] = expf(__ldg(s + i) - m) / __ldg(gsum + g);
    }
}

// ---------------- launch ----------------
extern "C" void kernel_launch(void* const* d_in, const int* in_sizes, int n_in,
                              void* d_out, int out_size) {
    const float* question = (const float*)d_in[0];
    const float* nodes    = (const float*)d_in[1];
    const float* edges    = (const float*)d_in[2];
    const float* W_nq     = (const float*)d_in[3];
    const float* b_nq     = (const float*)d_in[4];
    const float* W_n      = (const float*)d_in[5];
    const float* b_n      = (const float*)d_in[6];
    const float* w_nv     = (const float*)d_in[7];
    // d_in[8] = b_nv — softmax shift-invariant, unused
    const float* W_eq     = (const float*)d_in[9];
    const float* b_eq     = (const float*)d_in[10];
    const float* W_e      = (const float*)d_in[11];
    const float* b_e      = (const float*)d_in[12];
    const float* w_ev     = (const float*)d_in[13];
    // d_in[14] = b_ev — unused
    const int* node_gid   = (const int*)d_in[15];
    const int* edge_gid   = (const int*)d_in[16];
    float* out = (float*)d_out;

    float *qn, *qe, *sn, *se, *mx, *sm;
    __nv_bfloat16 *wtn, *wte;
    cudaGetSymbolAddress((void**)&qn,  g_qn);
    cudaGetSymbolAddress((void**)&qe,  g_qe);
    cudaGetSymbolAddress((void**)&wtn, g_wtn);
    cudaGetSymbolAddress((void**)&wte, g_wte);
    cudaGetSymbolAddress((void**)&sn,  g_sn);
    cudaGetSymbolAddress((void**)&se,  g_se);
    cudaGetSymbolAddress((void**)&mx,  g_max);
    cudaGetSymbolAddress((void**)&sm,  g_sum);

    cudaFuncSetAttribute(k_main, cudaFuncAttributeMaxDynamicSharedMemorySize, SMEM_BYTES);

    k_zero<<<TE_ / 512, 512>>>(sn, se, mx, sm);
    k_transpose<<<dim3(16, 16), dim3(32, 8)>>>(W_n, wtn);
    k_transpose<<<dim3(16, 16), dim3(32, 8)>>>(W_e, wte);
    k_qproj<<<B_, 512>>>(question, W_nq, b_nq, b_n, qn);
    k_qproj<<<B_, 512>>>(question, W_eq, b_eq, b_e, qe);

    k_main<<<dim3(4, TN_ / 128), 256, SMEM_BYTES>>>(nodes, node_gid, wtn, qn, w_nv, sn);
    k_main<<<dim3(4, TE_ / 128), 256, SMEM_BYTES>>>(edges, edge_gid, wte, qe, w_ev, se);

    k_max<<<TN_ / 256, 256>>>(sn, node_gid, mx,      TN_);
    k_max<<<TE_ / 256, 256>>>(se, edge_gid, mx + 64, TE_);
    k_sumexp<<<TN_ / 256, 256>>>(sn, node_gid, mx,      sm,      TN_);
    k_sumexp<<<TE_ / 256, 256>>>(se, edge_gid, mx + 64, sm + 64, TE_);
    k_norm<<<TN_ / 256, 256>>>(sn, node_gid, mx,      sm,      out,       TN_);
    k_norm<<<TE_ / 256, 256>>>(se, edge_gid, mx + 64, sm + 64, out + TN_, TE_);
}

// round 4
// speedup vs baseline: 1.5835x; 1.0650x over previous
#include <cuda_runtime.h>
#include <cuda_bf16.h>
#include <cstdint>

#define DINLINE __device__ __forceinline__

// ---------------- problem sizes ----------------
#define B_  64
#define TN_ 131072
#define TE_ 262144
#define QD_ 768
#define PD_ 512
#define KD_ 512

// ---------------- device scratch ----------------
__device__ float g_qn[B_ * PD_];
__device__ float g_qe[B_ * PD_];
__device__ __nv_bfloat16 g_wtn[PD_ * KD_];   // W_n transposed [P][K], bf16
__device__ __nv_bfloat16 g_wte[PD_ * KD_];
__device__ float g_sn[TN_];
__device__ float g_se[TE_];
__device__ float g_max[128];   // encoded-uint monotonic floats
__device__ float g_sum[128];

// ---------------- helpers ----------------
DINLINE unsigned fenc(float x) {
    unsigned u = __float_as_uint(x);
    return (u & 0x80000000u) ? ~u : (u | 0x80000000u);
}
DINLINE float fdec(unsigned e) {
    return (e & 0x80000000u) ? __uint_as_float(e ^ 0x80000000u)
                             : __uint_as_float(~e);
}

DINLINE void cp16(uint32_t s, const void* g) {
    asm volatile("cp.async.cg.shared.global [%0], [%1], 16;"
                 :: "r"(s), "l"(g) : "memory");
}
DINLINE void cp_commit() { asm volatile("cp.async.commit_group;" ::: "memory"); }
template<int N> DINLINE void cp_wait() {
    asm volatile("cp.async.wait_group %0;" :: "n"(N) : "memory");
}

DINLINE uint32_t smem_u32(const void* p) {
    uint32_t a;
    asm("{ .reg .u64 t; cvta.to.shared.u64 t, %1; cvt.u32.u64 %0, t; }"
        : "=r"(a) : "l"(p));
    return a;
}

DINLINE void mma_bf16(float* c, const uint32_t* a, const uint32_t* b) {
    asm volatile(
        "mma.sync.aligned.m16n8k16.row.col.f32.bf16.bf16.f32 "
        "{%0,%1,%2,%3}, {%4,%5,%6,%7}, {%8,%9}, {%0,%1,%2,%3};"
        : "+f"(c[0]), "+f"(c[1]), "+f"(c[2]), "+f"(c[3])
        : "r"(a[0]), "r"(a[1]), "r"(a[2]), "r"(a[3]),
          "r"(b[0]), "r"(b[1]));
}

DINLINE uint32_t pack_bf16x2(float lo, float hi) {
    __nv_bfloat162 v = __float22bfloat162_rn(make_float2(lo, hi));
    return *reinterpret_cast<uint32_t*>(&v);
}

// ---------------- main fused GEMM ----------------
// Tile: M=256 (blockIdx.y), N=128 (blockIdx.x in 0..3), K=512 in 16 chunks of 32.
// 8 warps: 4 wm x 2 wn, warp tile 64x64.
// SMEM (bf16, 80B padded rows):
//   A: 2 x (256 x 80B = 20480)  @ 0
//   B: 3 x (128 x 80B = 10240)  @ 40960
//   s_sm: 256 floats            @ 71680
#define ROWB   80u
#define ATILE  20480u
#define BTILE  10240u
#define BOFF   40960u
#define SM_OFF 71680u
#define SMEM_BYTES (71680 + 1024)

__global__ void __launch_bounds__(256, 1) k_main(
    const float* __restrict__ A, const int* __restrict__ gid,
    const __nv_bfloat16* __restrict__ Wt, const float* __restrict__ qeff,
    const float* __restrict__ wv, float* __restrict__ sOut)
{
    extern __shared__ char smem[];
    float* s_sm = reinterpret_cast<float*>(smem + SM_OFF);

    const int tid  = threadIdx.x;
    const int lane = tid & 31;
    const int warp = tid >> 5;
    const int wm   = warp & 3;   // M block of 64
    const int wn   = warp >> 2;  // N block of 64

    const int mBase = blockIdx.y * 256;
    const int nBase = blockIdx.x * 128;

    const uint32_t sb = smem_u32(smem);

    s_sm[tid] = 0.f;

    // ---- A loader: 256 rows x 32 f32 per chunk; thread: 8 float4
    // rows (tid>>3) + i*32, quad (tid&7)
    const int aRow = tid >> 3;
    const int aQ   = tid & 7;
    const float* Abase = A + (size_t)(mBase + aRow) * KD_ + aQ * 4;

    float4 ra[8];
    auto ldA = [&](int kc) {
        const float* p = Abase + kc * 32;
#pragma unroll
        for (int i = 0; i < 8; ++i)
            ra[i] = *reinterpret_cast<const float4*>(p + (size_t)i * 32 * KD_);
    };
    auto stsA = [&](int buf) {
        const uint32_t base = sb + buf * ATILE + aRow * ROWB + aQ * 8;
#pragma unroll
        for (int i = 0; i < 8; ++i) {
            uint32_t lo = pack_bf16x2(ra[i].x, ra[i].y);
            uint32_t hi = pack_bf16x2(ra[i].z, ra[i].w);
            asm volatile("st.shared.v2.b32 [%0], {%1,%2};"
                         :: "r"(base + i * 32 * ROWB), "r"(lo), "r"(hi) : "memory");
        }
    };
    // B: 128 n-rows x 32 bf16 per chunk = 8KB = 512 x 16B; thread does 2 cp16
    const int bIdx0 = tid * 2;
    auto cpB = [&](int slot, int kc) {
#pragma unroll
        for (int j = 0; j < 2; ++j) {
            int idx = bIdx0 + j;
            int n = idx >> 2, g = idx & 3;
            cp16(sb + BOFF + slot * BTILE + n * ROWB + g * 16,
                 Wt + (size_t)(nBase + n) * KD_ + kc * 32 + g * 8);
        }
        cp_commit();
    };

    float c[4][8][4];
#pragma unroll
    for (int mt = 0; mt < 4; ++mt)
#pragma unroll
        for (int nt = 0; nt < 8; ++nt)
#pragma unroll
            for (int i = 0; i < 4; ++i) c[mt][nt][i] = 0.f;

    ldA(0);
    cpB(0, 0);
    cpB(1, 1);

    const uint32_t aFragOff = (wm * 64 + (lane >> 2)) * ROWB + (lane & 3) * 4;
    const uint32_t bFragOff = (wn * 64 + (lane >> 2)) * ROWB + (lane & 3) * 4;

#pragma unroll 1
    for (int kc = 0; kc < 16; ++kc) {
        const int abuf = kc & 1;
        stsA(abuf);
        if (kc + 1 < 16) { ldA(kc + 1); cp_wait<1>(); }
        else             { cp_wait<0>(); }
        __syncthreads();
        if (kc + 2 < 16) cpB((kc + 2) % 3, kc + 2);

        const uint32_t aT = sb + abuf * ATILE + aFragOff;
        const uint32_t bT = sb + BOFF + (kc % 3) * BTILE + bFragOff;

#pragma unroll
        for (int ks = 0; ks < 2; ++ks) {
            const uint32_t ko = ks * 32;
            uint32_t a[4][4];
#pragma unroll
            for (int mt = 0; mt < 4; ++mt) {
                const uint32_t r = aT + mt * 16 * ROWB + ko;
                asm volatile("ld.shared.b32 %0, [%1];" : "=r"(a[mt][0]) : "r"(r));
                asm volatile("ld.shared.b32 %0, [%1];" : "=r"(a[mt][1]) : "r"(r + 8 * ROWB));
                asm volatile("ld.shared.b32 %0, [%1];" : "=r"(a[mt][2]) : "r"(r + 16));
                asm volatile("ld.shared.b32 %0, [%1];" : "=r"(a[mt][3]) : "r"(r + 8 * ROWB + 16));
            }
            uint32_t b[8][2];
#pragma unroll
            for (int nt = 0; nt < 8; ++nt) {
                const uint32_t nb = bT + nt * 8 * ROWB + ko;
                asm volatile("ld.shared.b32 %0, [%1];" : "=r"(b[nt][0]) : "r"(nb));
                asm volatile("ld.shared.b32 %0, [%1];" : "=r"(b[nt][1]) : "r"(nb + 16));
            }
#pragma unroll
            for (int mt = 0; mt < 4; ++mt)
#pragma unroll
                for (int nt = 0; nt < 8; ++nt)
                    mma_bf16(c[mt][nt], a[mt], b[nt]);
        }
    }
    __syncthreads();

    // ---- epilogue: s[m] += sum_n tanh(D + qeff[gid[m]][n]) * wv[n] ----
    const int n0 = wn * 64 + 2 * (lane & 3);
#pragma unroll
    for (int mt = 0; mt < 4; ++mt) {
#pragma unroll
        for (int h = 0; h < 2; ++h) {
            const int row = wm * 64 + mt * 16 + (lane >> 2) + h * 8;
            const int g = __ldg(gid + mBase + row);
            const float* qrow = qeff + (size_t)g * PD_ + nBase;
            float s = 0.f;
#pragma unroll
            for (int nt = 0; nt < 8; ++nt) {
                const int nn = n0 + nt * 8;
                float2 q2 = *reinterpret_cast<const float2*>(qrow + nn);
                float2 w2 = *reinterpret_cast<const float2*>(wv + nBase + nn);
                float x0 = tanhf(c[mt][nt][h * 2 + 0] + q2.x);
                float x1 = tanhf(c[mt][nt][h * 2 + 1] + q2.y);
                s = fmaf(x0, w2.x, s);
                s = fmaf(x1, w2.y, s);
            }
            s += __shfl_xor_sync(0xffffffffu, s, 1);
            s += __shfl_xor_sync(0xffffffffu, s, 2);
            if ((lane & 3) == 0) atomicAdd(&s_sm[row], s);
        }
    }
    __syncthreads();
    atomicAdd(&sOut[mBase + tid], s_sm[tid]);
}

// ---------------- small kernels ----------------
__global__ void k_zero(float* sn, float* se, float* gmax, float* gsum,
                       float* qn, float* qe) {
    int i = blockIdx.x * blockDim.x + threadIdx.x;
    if (i < TN_) sn[i] = 0.f;
    if (i < TE_) se[i] = 0.f;
    if (i < B_ * PD_) { qn[i] = 0.f; qe[i] = 0.f; }
    if (i < 128) { reinterpret_cast<unsigned*>(gmax)[i] = 0u; gsum[i] = 0.f; }
}

// Wt[p][k] = bf16(W[k][p])  (512x512)
__global__ void k_transpose(const float* __restrict__ W, __nv_bfloat16* __restrict__ Wt) {
    __shared__ float tile[32][33];
    int x = blockIdx.x * 32 + threadIdx.x;   // p
    int y = blockIdx.y * 32 + threadIdx.y;   // k
#pragma unroll
    for (int j = 0; j < 32; j += 8)
        tile[threadIdx.y + j][threadIdx.x] = W[(y + j) * 512 + x];
    __syncthreads();
    int xo = blockIdx.y * 32 + threadIdx.x;  // k
    int yo = blockIdx.x * 32 + threadIdx.y;  // p
#pragma unroll
    for (int j = 0; j < 32; j += 8)
        Wt[(yo + j) * 512 + xo] = __float2bfloat16(tile[threadIdx.x][threadIdx.y + j]);
}

// split-k qproj: grid (B_, 8); block (b, ks) covers k-slice of 96.
// qeff[b][p] += sum_{k in slice} q[b,k]*Wq[k,p]  (+ biases on ks==0)
__global__ void __launch_bounds__(256) k_qproj(
    const float* __restrict__ q, const float* __restrict__ Wq,
    const float* __restrict__ bq, const float* __restrict__ bh,
    float* __restrict__ out) {
    __shared__ float qs[96];
    const int b = blockIdx.x, ks = blockIdx.y;
    const int k0 = ks * 96;
    const int t = threadIdx.x;
    if (t < 96) qs[t] = q[b * QD_ + k0 + t];
    __syncthreads();
    const int p0 = t, p1 = t + 256;
    float a0 = 0.f, a1 = 0.f;
#pragma unroll 4
    for (int k = 0; k < 96; ++k) {
        const float* wrow = Wq + (size_t)(k0 + k) * 512;
        a0 = fmaf(qs[k], __ldg(wrow + p0), a0);
        a1 = fmaf(qs[k], __ldg(wrow + p1), a1);
    }
    if (ks == 0) {
        a0 += __ldg(bq + p0) + __ldg(bh + p0);
        a1 += __ldg(bq + p1) + __ldg(bh + p1);
    }
    atomicAdd(out + b * 512 + p0, a0);
    atomicAdd(out + b * 512 + p1, a1);
}

__global__ void k_max(const float* __restrict__ s, const int* __restrict__ gid,
                      float* __restrict__ gmax, int n) {
    __shared__ unsigned sm[64];
    int t = threadIdx.x;
    if (t < 64) sm[t] = 0u;
    __syncthreads();
    int i = blockIdx.x * blockDim.x + t;
    if (i < n) atomicMax(&sm[__ldg(gid + i)], fenc(__ldg(s + i)));
    __syncthreads();
    if (t < 64 && sm[t] != 0u)
        atomicMax(reinterpret_cast<unsigned*>(gmax) + t, sm[t]);
}

__global__ void k_sumexp(const float* __restrict__ s, const int* __restrict__ gid,
                         const float* __restrict__ gmax, float* __restrict__ gsum, int n) {
    __shared__ float ssum[64];
    int t = threadIdx.x;
    if (t < 64) ssum[t] = 0.f;
    __syncthreads();
    int i = blockIdx.x * blockDim.x + t;
    if (i < n) {
        int g = __ldg(gid + i);
        float m = fdec(reinterpret_cast<const unsigned*>(gmax)[g]);
        atomicAdd(&ssum[g], expf(__ldg(s + i) - m));
    }
    __syncthreads();
    if (t < 64 && ssum[t] != 0.f) atomicAdd(&gsum[t], ssum[t]);
}

__global__ void k_norm(const float* __restrict__ s, const int* __restrict__ gid,
                       const float* __restrict__ gmax, const float* __restrict__ gsum,
                       float* __restrict__ out, int n) {
    int i = blockIdx.x * blockDim.x + threadIdx.x;
    if (i < n) {
        int g = __ldg(gid + i);
        float m = fdec(reinterpret_cast<const unsigned*>(gmax)[g]);
        out[i] = expf(__ldg(s + i) - m) / __ldg(gsum + g);
    }
}

// ---------------- launch ----------------
extern "C" void kernel_launch(void* const* d_in, const int* in_sizes, int n_in,
                              void* d_out, int out_size) {
    const float* question = (const float*)d_in[0];
    const float* nodes    = (const float*)d_in[1];
    const float* edges    = (const float*)d_in[2];
    const float* W_nq     = (const float*)d_in[3];
    const float* b_nq     = (const float*)d_in[4];
    const float* W_n      = (const float*)d_in[5];
    const float* b_n      = (const float*)d_in[6];
    const float* w_nv     = (const float*)d_in[7];
    // d_in[8] = b_nv — softmax shift-invariant, unused
    const float* W_eq     = (const float*)d_in[9];
    const float* b_eq     = (const float*)d_in[10];
    const float* W_e      = (const float*)d_in[11];
    const float* b_e      = (const float*)d_in[12];
    const float* w_ev     = (const float*)d_in[13];
    // d_in[14] = b_ev — unused
    const int* node_gid   = (const int*)d_in[15];
    const int* edge_gid   = (const int*)d_in[16];
    float* out = (float*)d_out;

    float *qn, *qe, *sn, *se, *mx, *sm;
    __nv_bfloat16 *wtn, *wte;
    cudaGetSymbolAddress((void**)&qn,  g_qn);
    cudaGetSymbolAddress((void**)&qe,  g_qe);
    cudaGetSymbolAddress((void**)&wtn, g_wtn);
    cudaGetSymbolAddress((void**)&wte, g_wte);
    cudaGetSymbolAddress((void**)&sn,  g_sn);
    cudaGetSymbolAddress((void**)&se,  g_se);
    cudaGetSymbolAddress((void**)&mx,  g_max);
    cudaGetSymbolAddress((void**)&sm,  g_sum);

    cudaFuncSetAttribute(k_main, cudaFuncAttributeMaxDynamicSharedMemorySize, SMEM_BYTES);

    k_zero<<<TE_ / 512, 512>>>(sn, se, mx, sm, qn, qe);
    k_transpose<<<dim3(16, 16), dim3(32, 8)>>>(W_n, wtn);
    k_transpose<<<dim3(16, 16), dim3(32, 8)>>>(W_e, wte);
    k_qproj<<<dim3(B_, 8), 256>>>(question, W_nq, b_nq, b_n, qn);
    k_qproj<<<dim3(B_, 8), 256>>>(question, W_eq, b_eq, b_e, qe);

    k_main<<<dim3(4, TN_ / 256), 256, SMEM_BYTES>>>(nodes, node_gid, wtn, qn, w_nv, sn);
    k_main<<<dim3(4, TE_ / 256), 256, SMEM_BYTES>>>(edges, edge_gid, wte, qe, w_ev, se);

    k_max<<<TN_ / 256, 256>>>(sn, node_gid, mx,      TN_);
    k_max<<<TE_ / 256, 256>>>(se, edge_gid, mx + 64, TE_);
    k_sumexp<<<TN_ / 256, 256>>>(sn, node_gid, mx,      sm,      TN_);
    k_sumexp<<<TE_ / 256, 256>>>(se, edge_gid, mx + 64, sm + 64, TE_);
    k_norm<<<TN_ / 256, 256>>>(sn, node_gid, mx,      sm,      out,       TN_);
    k_norm<<<TE_ / 256, 256>>>(se, edge_gid, mx + 64, sm + 64, out + TN_, TE_);
}

// round 5
// speedup vs baseline: 1.6571x; 1.0465x over previous
#include <cuda_runtime.h>
#include <cuda_bf16.h>
#include <cstdint>

#define DINLINE __device__ __forceinline__

// ---------------- problem sizes ----------------
#define B_  64
#define TN_ 131072
#define TE_ 262144
#define QD_ 768
#define PD_ 512
#define KD_ 512

// ---------------- device scratch ----------------
__device__ float g_qn[B_ * PD_];
__device__ float g_qe[B_ * PD_];
__device__ __nv_bfloat16 g_wtn[PD_ * KD_];   // W_n transposed [P][K], bf16
__device__ __nv_bfloat16 g_wte[PD_ * KD_];
__device__ float g_sn[TN_];
__device__ float g_se[TE_];

// ---------------- helpers ----------------
DINLINE void cp16(uint32_t s, const void* g) {
    asm volatile("cp.async.cg.shared.global [%0], [%1], 16;"
                 :: "r"(s), "l"(g) : "memory");
}
DINLINE void cp_commit() { asm volatile("cp.async.commit_group;" ::: "memory"); }
template<int N> DINLINE void cp_wait() {
    asm volatile("cp.async.wait_group %0;" :: "n"(N) : "memory");
}

DINLINE uint32_t smem_u32(const void* p) {
    uint32_t a;
    asm("{ .reg .u64 t; cvta.to.shared.u64 t, %1; cvt.u32.u64 %0, t; }"
        : "=r"(a) : "l"(p));
    return a;
}

DINLINE void mma_bf16(float* c, const uint32_t* a, const uint32_t* b) {
    asm volatile(
        "mma.sync.aligned.m16n8k16.row.col.f32.bf16.bf16.f32 "
        "{%0,%1,%2,%3}, {%4,%5,%6,%7}, {%8,%9}, {%0,%1,%2,%3};"
        : "+f"(c[0]), "+f"(c[1]), "+f"(c[2]), "+f"(c[3])
        : "r"(a[0]), "r"(a[1]), "r"(a[2]), "r"(a[3]),
          "r"(b[0]), "r"(b[1]));
}

DINLINE uint32_t pack_bf16x2(float lo, float hi) {
    __nv_bfloat162 v = __float22bfloat162_rn(make_float2(lo, hi));
    return *reinterpret_cast<uint32_t*>(&v);
}

// ---------------- main fused GEMM ----------------
// Tile: M=256, N=128 (blockIdx.x in 0..3), K=512 in 16 chunks of 32.
// blockIdx.y in [0,1536): y<512 -> nodes tile y; y>=512 -> edges tile y-512.
// 8 warps: 4 wm x 2 wn, warp tile 64x64.
// SMEM (bf16, 80B padded rows):
//   A: 2 x (256 x 80B = 20480)  @ 0
//   B: 3 x (128 x 80B = 10240)  @ 40960
//   s_sm: 256 floats            @ 71680
#define ROWB   80u
#define ATILE  20480u
#define BTILE  10240u
#define BOFF   40960u
#define SM_OFF 71680u
#define SMEM_BYTES (71680 + 1024)
#define NYN 512              // node tiles in y

__global__ void __launch_bounds__(256, 1) k_main(
    const float* __restrict__ An, const float* __restrict__ Ae,
    const int* __restrict__ gidN, const int* __restrict__ gidE,
    const __nv_bfloat16* __restrict__ WtN, const __nv_bfloat16* __restrict__ WtE,
    const float* __restrict__ qN, const float* __restrict__ qE,
    const float* __restrict__ wvN, const float* __restrict__ wvE,
    float* __restrict__ sN, float* __restrict__ sE)
{
    extern __shared__ char smem[];
    float* s_sm = reinterpret_cast<float*>(smem + SM_OFF);

    const bool isNode = blockIdx.y < NYN;
    const int  ty     = isNode ? blockIdx.y : blockIdx.y - NYN;
    const float* __restrict__ A    = isNode ? An   : Ae;
    const int*   __restrict__ gid  = isNode ? gidN : gidE;
    const __nv_bfloat16* __restrict__ Wt = isNode ? WtN : WtE;
    const float* __restrict__ qeff = isNode ? qN   : qE;
    const float* __restrict__ wv   = isNode ? wvN  : wvE;
    float*       __restrict__ sOut = isNode ? sN   : sE;

    const int tid  = threadIdx.x;
    const int lane = tid & 31;
    const int warp = tid >> 5;
    const int wm   = warp & 3;   // M block of 64
    const int wn   = warp >> 2;  // N block of 64

    const int mBase = ty * 256;
    const int nBase = blockIdx.x * 128;

    const uint32_t sb = smem_u32(smem);

    s_sm[tid] = 0.f;

    // ---- A loader: 256 rows x 32 f32 per chunk; thread: 8 float4
    const int aRow = tid >> 3;
    const int aQ   = tid & 7;
    const float* Abase = A + (size_t)(mBase + aRow) * KD_ + aQ * 4;

    float4 ra[8];
    auto ldA = [&](int kc) {
        const float* p = Abase + kc * 32;
#pragma unroll
        for (int i = 0; i < 8; ++i)
            ra[i] = *reinterpret_cast<const float4*>(p + (size_t)i * 32 * KD_);
    };
    auto stsA = [&](int buf) {
        const uint32_t base = sb + buf * ATILE + aRow * ROWB + aQ * 8;
#pragma unroll
        for (int i = 0; i < 8; ++i) {
            uint32_t lo = pack_bf16x2(ra[i].x, ra[i].y);
            uint32_t hi = pack_bf16x2(ra[i].z, ra[i].w);
            asm volatile("st.shared.v2.b32 [%0], {%1,%2};"
                         :: "r"(base + i * 32 * ROWB), "r"(lo), "r"(hi) : "memory");
        }
    };
    // B: 128 n-rows x 32 bf16 per chunk = 8KB = 512 x 16B; thread does 2 cp16
    const int bIdx0 = tid * 2;
    auto cpB = [&](int slot, int kc) {
#pragma unroll
        for (int j = 0; j < 2; ++j) {
            int idx = bIdx0 + j;
            int n = idx >> 2, g = idx & 3;
            cp16(sb + BOFF + slot * BTILE + n * ROWB + g * 16,
                 Wt + (size_t)(nBase + n) * KD_ + kc * 32 + g * 8);
        }
        cp_commit();
    };

    float c[4][8][4];
#pragma unroll
    for (int mt = 0; mt < 4; ++mt)
#pragma unroll
        for (int nt = 0; nt < 8; ++nt)
#pragma unroll
            for (int i = 0; i < 4; ++i) c[mt][nt][i] = 0.f;

    ldA(0);
    cpB(0, 0);
    cpB(1, 1);

    const uint32_t aFragOff = (wm * 64 + (lane >> 2)) * ROWB + (lane & 3) * 4;
    const uint32_t bFragOff = (wn * 64 + (lane >> 2)) * ROWB + (lane & 3) * 4;

#pragma unroll 1
    for (int kc = 0; kc < 16; ++kc) {
        const int abuf = kc & 1;
        stsA(abuf);
        if (kc + 1 < 16) { ldA(kc + 1); cp_wait<1>(); }
        else             { cp_wait<0>(); }
        __syncthreads();
        if (kc + 2 < 16) cpB((kc + 2) % 3, kc + 2);

        const uint32_t aT = sb + abuf * ATILE + aFragOff;
        const uint32_t bT = sb + BOFF + (kc % 3) * BTILE + bFragOff;

#pragma unroll
        for (int ks = 0; ks < 2; ++ks) {
            const uint32_t ko = ks * 32;
            uint32_t a[4][4];
#pragma unroll
            for (int mt = 0; mt < 4; ++mt) {
                const uint32_t r = aT + mt * 16 * ROWB + ko;
                asm volatile("ld.shared.b32 %0, [%1];" : "=r"(a[mt][0]) : "r"(r));
                asm volatile("ld.shared.b32 %0, [%1];" : "=r"(a[mt][1]) : "r"(r + 8 * ROWB));
                asm volatile("ld.shared.b32 %0, [%1];" : "=r"(a[mt][2]) : "r"(r + 16));
                asm volatile("ld.shared.b32 %0, [%1];" : "=r"(a[mt][3]) : "r"(r + 8 * ROWB + 16));
            }
            uint32_t b[8][2];
#pragma unroll
            for (int nt = 0; nt < 8; ++nt) {
                const uint32_t nb = bT + nt * 8 * ROWB + ko;
                asm volatile("ld.shared.b32 %0, [%1];" : "=r"(b[nt][0]) : "r"(nb));
                asm volatile("ld.shared.b32 %0, [%1];" : "=r"(b[nt][1]) : "r"(nb + 16));
            }
#pragma unroll
            for (int mt = 0; mt < 4; ++mt)
#pragma unroll
                for (int nt = 0; nt < 8; ++nt)
                    mma_bf16(c[mt][nt], a[mt], b[nt]);
        }
    }
    __syncthreads();

    // ---- epilogue: s[m] += sum_n tanh(D + qeff[gid[m]][n]) * wv[n] ----
    const int n0 = wn * 64 + 2 * (lane & 3);
#pragma unroll
    for (int mt = 0; mt < 4; ++mt) {
#pragma unroll
        for (int h = 0; h < 2; ++h) {
            const int row = wm * 64 + mt * 16 + (lane >> 2) + h * 8;
            const int g = __ldg(gid + mBase + row);
            const float* qrow = qeff + (size_t)g * PD_ + nBase;
            float s = 0.f;
#pragma unroll
            for (int nt = 0; nt < 8; ++nt) {
                const int nn = n0 + nt * 8;
                float2 q2 = *reinterpret_cast<const float2*>(qrow + nn);
                float2 w2 = *reinterpret_cast<const float2*>(wv + nBase + nn);
                float x0 = tanhf(c[mt][nt][h * 2 + 0] + q2.x);
                float x1 = tanhf(c[mt][nt][h * 2 + 1] + q2.y);
                s = fmaf(x0, w2.x, s);
                s = fmaf(x1, w2.y, s);
            }
            s += __shfl_xor_sync(0xffffffffu, s, 1);
            s += __shfl_xor_sync(0xffffffffu, s, 2);
            if ((lane & 3) == 0) atomicAdd(&s_sm[row], s);
        }
    }
    __syncthreads();
    atomicAdd(&sOut[mBase + tid], s_sm[tid]);
}

// ---------------- prep kernels ----------------
__global__ void k_zero(float* sn, float* se, float* qn, float* qe) {
    int i = blockIdx.x * blockDim.x + threadIdx.x;
    if (i < TN_) sn[i] = 0.f;
    if (i < TE_) se[i] = 0.f;
    if (i < B_ * PD_) { qn[i] = 0.f; qe[i] = 0.f; }
}

// Wt[p][k] = bf16(W[k][p])  (512x512), grid.z selects node/edge
__global__ void k_transpose(const float* __restrict__ Wn, const float* __restrict__ We,
                            __nv_bfloat16* __restrict__ WtN, __nv_bfloat16* __restrict__ WtE) {
    const float* W = blockIdx.z ? We : Wn;
    __nv_bfloat16* Wt = blockIdx.z ? WtE : WtN;
    __shared__ float tile[32][33];
    int x = blockIdx.x * 32 + threadIdx.x;   // p
    int y = blockIdx.y * 32 + threadIdx.y;   // k
#pragma unroll
    for (int j = 0; j < 32; j += 8)
        tile[threadIdx.y + j][threadIdx.x] = W[(y + j) * 512 + x];
    __syncthreads();
    int xo = blockIdx.y * 32 + threadIdx.x;  // k
    int yo = blockIdx.x * 32 + threadIdx.y;  // p
#pragma unroll
    for (int j = 0; j < 32; j += 8)
        Wt[(yo + j) * 512 + xo] = __float2bfloat16(tile[threadIdx.x][threadIdx.y + j]);
}

// split-k qproj, grid (B_, 8, 2): z selects node/edge weights.
__global__ void __launch_bounds__(256) k_qproj(
    const float* __restrict__ q,
    const float* __restrict__ WqN, const float* __restrict__ bqN, const float* __restrict__ bhN,
    const float* __restrict__ WqE, const float* __restrict__ bqE, const float* __restrict__ bhE,
    float* __restrict__ outN, float* __restrict__ outE) {
    const float* Wq = blockIdx.z ? WqE : WqN;
    const float* bq = blockIdx.z ? bqE : bqN;
    const float* bh = blockIdx.z ? bhE : bhN;
    float* out = blockIdx.z ? outE : outN;
    __shared__ float qs[96];
    const int b = blockIdx.x, ks = blockIdx.y;
    const int k0 = ks * 96;
    const int t = threadIdx.x;
    if (t < 96) qs[t] = q[b * QD_ + k0 + t];
    __syncthreads();
    const int p0 = t, p1 = t + 256;
    float a0 = 0.f, a1 = 0.f;
#pragma unroll 4
    for (int k = 0; k < 96; ++k) {
        const float* wrow = Wq + (size_t)(k0 + k) * 512;
        a0 = fmaf(qs[k], __ldg(wrow + p0), a0);
        a1 = fmaf(qs[k], __ldg(wrow + p1), a1);
    }
    if (ks == 0) {
        a0 += __ldg(bq + p0) + __ldg(bh + p0);
        a1 += __ldg(bq + p1) + __ldg(bh + p1);
    }
    atomicAdd(out + b * 512 + p0, a0);
    atomicAdd(out + b * 512 + p1, a1);
}

// ---------------- fused per-graph softmax (gid sorted -> contiguous segments) ----
// grid 128: block g<64 -> nodes graph g; else edges graph g-64.
__global__ void __launch_bounds__(256) k_soft(
    const float* __restrict__ sn, const float* __restrict__ se,
    const int* __restrict__ gidN, const int* __restrict__ gidE,
    float* __restrict__ out) {
    const bool isNode = blockIdx.x < 64;
    const int g = isNode ? blockIdx.x : blockIdx.x - 64;
    const float* s  = isNode ? sn : se;
    const int* gid  = isNode ? gidN : gidE;
    const int n     = isNode ? TN_ : TE_;
    float* o        = out + (isNode ? 0 : TN_);

    const int t = threadIdx.x;
    __shared__ float red[256];
    __shared__ int bounds[2];

    // binary search segment bounds (threads 0 and 1)
    if (t < 2) {
        int target = g + t;           // lower_bound of g (t=0) and g+1 (t=1)
        int lo = 0, hi = n;
        while (lo < hi) {
            int mid = (lo + hi) >> 1;
            if (__ldg(gid + mid) < target) lo = mid + 1; else hi = mid;
        }
        bounds[t] = lo;
    }
    __syncthreads();
    const int lo = bounds[0], hi = bounds[1];

    // pass 1: max
    float m = -3.0e38f;
    for (int i = lo + t; i < hi; i += 256) m = fmaxf(m, __ldg(s + i));
    red[t] = m;
    __syncthreads();
#pragma unroll
    for (int st = 128; st >= 1; st >>= 1) {
        if (t < st) red[t] = fmaxf(red[t], red[t + st]);
        __syncthreads();
    }
    m = red[0];
    __syncthreads();

    // pass 2: sum exp
    float z = 0.f;
    for (int i = lo + t; i < hi; i += 256) z += expf(__ldg(s + i) - m);
    red[t] = z;
    __syncthreads();
#pragma unroll
    for (int st = 128; st >= 1; st >>= 1) {
        if (t < st) red[t] += red[t + st];
        __syncthreads();
    }
    const float rz = 1.f / red[0];

    // pass 3: normalize
    for (int i = lo + t; i < hi; i += 256)
        o[i] = expf(__ldg(s + i) - m) * rz;
}

// ---------------- launch ----------------
extern "C" void kernel_launch(void* const* d_in, const int* in_sizes, int n_in,
                              void* d_out, int out_size) {
    const float* question = (const float*)d_in[0];
    const float* nodes    = (const float*)d_in[1];
    const float* edges    = (const float*)d_in[2];
    const float* W_nq     = (const float*)d_in[3];
    const float* b_nq     = (const float*)d_in[4];
    const float* W_n      = (const float*)d_in[5];
    const float* b_n      = (const float*)d_in[6];
    const float* w_nv     = (const float*)d_in[7];
    // d_in[8] = b_nv — softmax shift-invariant, unused
    const float* W_eq     = (const float*)d_in[9];
    const float* b_eq     = (const float*)d_in[10];
    const float* W_e      = (const float*)d_in[11];
    const float* b_e      = (const float*)d_in[12];
    const float* w_ev     = (const float*)d_in[13];
    // d_in[14] = b_ev — unused
    const int* node_gid   = (const int*)d_in[15];
    const int* edge_gid   = (const int*)d_in[16];
    float* out = (float*)d_out;

    float *qn, *qe, *sn, *se;
    __nv_bfloat16 *wtn, *wte;
    cudaGetSymbolAddress((void**)&qn,  g_qn);
    cudaGetSymbolAddress((void**)&qe,  g_qe);
    cudaGetSymbolAddress((void**)&wtn, g_wtn);
    cudaGetSymbolAddress((void**)&wte, g_wte);
    cudaGetSymbolAddress((void**)&sn,  g_sn);
    cudaGetSymbolAddress((void**)&se,  g_se);

    cudaFuncSetAttribute(k_main, cudaFuncAttributeMaxDynamicSharedMemorySize, SMEM_BYTES);

    k_zero<<<TE_ / 512, 512>>>(sn, se, qn, qe);
    k_transpose<<<dim3(16, 16, 2), dim3(32, 8)>>>(W_n, W_e, wtn, wte);
    k_qproj<<<dim3(B_, 8, 2), 256>>>(question,
                                     W_nq, b_nq, b_n,
                                     W_eq, b_eq, b_e, qn, qe);

    k_main<<<dim3(4, NYN + TE_ / 256), 256, SMEM_BYTES>>>(
        nodes, edges, node_gid, edge_gid, wtn, wte, qn, qe, w_nv, w_ev, sn, se);

    k_soft<<<128, 256>>>(sn, se, node_gid, edge_gid, out);
}

// round 6
// speedup vs baseline: 1.8199x; 1.0982x over previous
#include <cuda_runtime.h>
#include <cuda_bf16.h>
#include <cstdint>

#define DINLINE __device__ __forceinline__

// ---------------- problem sizes ----------------
#define B_  64
#define TN_ 131072
#define TE_ 262144
#define QD_ 768
#define PD_ 512
#define KD_ 512

// ---------------- device scratch ----------------
__device__ float g_qn[B_ * PD_];
__device__ float g_qe[B_ * PD_];
__device__ __nv_bfloat16 g_wtn[PD_ * KD_];   // W_n transposed [P][K], bf16
__device__ __nv_bfloat16 g_wte[PD_ * KD_];
__device__ float g_sn[TN_];
__device__ float g_se[TE_];

// ---------------- helpers ----------------
DINLINE void cp16(uint32_t s, const void* g) {
    asm volatile("cp.async.cg.shared.global [%0], [%1], 16;"
                 :: "r"(s), "l"(g) : "memory");
}
DINLINE void cp_commit() { asm volatile("cp.async.commit_group;" ::: "memory"); }
template<int N> DINLINE void cp_wait() {
    asm volatile("cp.async.wait_group %0;" :: "n"(N) : "memory");
}

DINLINE uint32_t smem_u32(const void* p) {
    uint32_t a;
    asm("{ .reg .u64 t; cvta.to.shared.u64 t, %1; cvt.u32.u64 %0, t; }"
        : "=r"(a) : "l"(p));
    return a;
}

DINLINE void mma_bf16(float* c, const uint32_t* a, const uint32_t* b) {
    asm volatile(
        "mma.sync.aligned.m16n8k16.row.col.f32.bf16.bf16.f32 "
        "{%0,%1,%2,%3}, {%4,%5,%6,%7}, {%8,%9}, {%0,%1,%2,%3};"
        : "+f"(c[0]), "+f"(c[1]), "+f"(c[2]), "+f"(c[3])
        : "r"(a[0]), "r"(a[1]), "r"(a[2]), "r"(a[3]),
          "r"(b[0]), "r"(b[1]));
}

DINLINE void ldm_x4(uint32_t& r0, uint32_t& r1, uint32_t& r2, uint32_t& r3,
                    uint32_t addr) {
    asm volatile("ldmatrix.sync.aligned.m8n8.x4.shared.b16 {%0,%1,%2,%3}, [%4];"
                 : "=r"(r0), "=r"(r1), "=r"(r2), "=r"(r3) : "r"(addr));
}

DINLINE uint32_t pack_bf16x2(float lo, float hi) {
    __nv_bfloat162 v = __float22bfloat162_rn(make_float2(lo, hi));
    return *reinterpret_cast<uint32_t*>(&v);
}

// ---------------- main fused GEMM ----------------
// Tile: M=256, N=128 (blockIdx.x in 0..3), K=512 in 16 chunks of 32.
// blockIdx.y in [0,1536): y<512 -> nodes; else edges.
// 8 warps: 4 wm x 2 wn, warp tile 64x64.
// SMEM (bf16, 80B padded rows):
//   A: 2 x (256 x 80B = 20480)  @ 0
//   B: 3 x (128 x 80B = 10240)  @ 40960
//   s_sm: 256 floats            @ 71680
#define ROWB   80u
#define ATILE  20480u
#define BTILE  10240u
#define BOFF   40960u
#define SM_OFF 71680u
#define SMEM_BYTES (71680 + 1024)
#define NYN 512              // node tiles in y

__global__ void __launch_bounds__(256, 1) k_main(
    const float* __restrict__ An, const float* __restrict__ Ae,
    const int* __restrict__ gidN, const int* __restrict__ gidE,
    const __nv_bfloat16* __restrict__ WtN, const __nv_bfloat16* __restrict__ WtE,
    const float* __restrict__ qN, const float* __restrict__ qE,
    const float* __restrict__ wvN, const float* __restrict__ wvE,
    float* __restrict__ sN, float* __restrict__ sE)
{
    extern __shared__ char smem[];
    float* s_sm = reinterpret_cast<float*>(smem + SM_OFF);

    const bool isNode = blockIdx.y < NYN;
    const int  ty     = isNode ? blockIdx.y : blockIdx.y - NYN;
    const float* __restrict__ A    = isNode ? An   : Ae;
    const int*   __restrict__ gid  = isNode ? gidN : gidE;
    const __nv_bfloat16* __restrict__ Wt = isNode ? WtN : WtE;
    const float* __restrict__ qeff = isNode ? qN   : qE;
    const float* __restrict__ wv   = isNode ? wvN  : wvE;
    float*       __restrict__ sOut = isNode ? sN   : sE;

    const int tid  = threadIdx.x;
    const int lane = tid & 31;
    const int warp = tid >> 5;
    const int wm   = warp & 3;   // M block of 64
    const int wn   = warp >> 2;  // N block of 64

    const int mBase = ty * 256;
    const int nBase = blockIdx.x * 128;

    const uint32_t sb = smem_u32(smem);

    s_sm[tid] = 0.f;

    // ---- A loader: 256 rows x 32 f32 per chunk; thread: 8 float4
    const int aRow = tid >> 3;
    const int aQ   = tid & 7;
    const float* Abase = A + (size_t)(mBase + aRow) * KD_ + aQ * 4;

    float4 ra[8];
    auto ldA = [&](int kc) {
        const float* p = Abase + kc * 32;
#pragma unroll
        for (int i = 0; i < 8; ++i)
            ra[i] = *reinterpret_cast<const float4*>(p + (size_t)i * 32 * KD_);
    };
    auto stsA = [&](int buf) {
        const uint32_t base = sb + buf * ATILE + aRow * ROWB + aQ * 8;
#pragma unroll
        for (int i = 0; i < 8; ++i) {
            uint32_t lo = pack_bf16x2(ra[i].x, ra[i].y);
            uint32_t hi = pack_bf16x2(ra[i].z, ra[i].w);
            asm volatile("st.shared.v2.b32 [%0], {%1,%2};"
                         :: "r"(base + i * 32 * ROWB), "r"(lo), "r"(hi) : "memory");
        }
    };
    // B: 128 n-rows x 32 bf16 per chunk = 8KB = 512 x 16B; thread does 2 cp16
    const int bIdx0 = tid * 2;
    auto cpB = [&](int slot, int kc) {
#pragma unroll
        for (int j = 0; j < 2; ++j) {
            int idx = bIdx0 + j;
            int n = idx >> 2, g = idx & 3;
            cp16(sb + BOFF + slot * BTILE + n * ROWB + g * 16,
                 Wt + (size_t)(nBase + n) * KD_ + kc * 32 + g * 8);
        }
        cp_commit();
    };

    float c[4][8][4];
#pragma unroll
    for (int mt = 0; mt < 4; ++mt)
#pragma unroll
        for (int nt = 0; nt < 8; ++nt)
#pragma unroll
            for (int i = 0; i < 4; ++i) c[mt][nt][i] = 0.f;

    // ---- ldmatrix per-lane offsets ----
    // j = lane>>3 selects which of the 4 m8n8 matrices this lane addresses.
    const int j = lane >> 3;
    // A matrices per mt: m0=(r+0,klo) m1=(r+8,klo) m2=(r+0,khi) m3=(r+8,khi)
    const uint32_t aLane = (uint32_t)(wm * 64 + ((j & 1) << 3) + (lane & 7)) * ROWB
                         + (uint32_t)(j >> 1) * 16u;
    // B matrices per even p: m0=(n p,klo) m1=(n p,khi) m2=(n p+1,klo) m3=(n p+1,khi)
    const uint32_t bLane = (uint32_t)(wn * 64 + ((j >> 1) << 3) + (lane & 7)) * ROWB
                         + (uint32_t)(j & 1) * 16u;

    // ---- preamble ----
    ldA(0);
    cpB(0, 0);
    cpB(1, 1);
    stsA(0);
    ldA(1);
    cp_wait<1>();
    __syncthreads();

    auto mma_ks = [&](uint32_t aT2, uint32_t bT2, uint32_t ko) {
        uint32_t a[4][4];
#pragma unroll
        for (int mt = 0; mt < 4; ++mt)
            ldm_x4(a[mt][0], a[mt][1], a[mt][2], a[mt][3],
                   aT2 + mt * 16 * ROWB + ko);
        uint32_t b[8][2];
#pragma unroll
        for (int p = 0; p < 8; p += 2)
            ldm_x4(b[p][0], b[p][1], b[p + 1][0], b[p + 1][1],
                   bT2 + p * 8 * ROWB + ko);
#pragma unroll
        for (int mt = 0; mt < 4; ++mt)
#pragma unroll
            for (int nt = 0; nt < 8; ++nt)
                mma_bf16(c[mt][nt], a[mt], b[nt]);
    };

#pragma unroll 1
    for (int kc = 0; kc < 16; ++kc) {
        const int abuf = kc & 1;
        if (kc + 2 < 16) cpB((kc + 2) % 3, kc + 2);

        const uint32_t aT2 = sb + abuf * ATILE + aLane;
        const uint32_t bT2 = sb + BOFF + (kc % 3) * BTILE + bLane;

        mma_ks(aT2, bT2, 0);                 // ks = 0
        if (kc + 1 < 16) stsA(abuf ^ 1);     // STS next A chunk (overlaps MMA)
        if (kc + 2 < 16) ldA(kc + 2);        // LDG two chunks ahead
        mma_ks(aT2, bT2, 32);                // ks = 1

        if (kc + 2 < 16) cp_wait<1>(); else cp_wait<0>();
        __syncthreads();
    }

    // ---- epilogue: s[m] += sum_n tanh(D + qeff[gid[m]][n]) * wv[n] ----
    const int n0 = wn * 64 + 2 * (lane & 3);
#pragma unroll
    for (int mt = 0; mt < 4; ++mt) {
#pragma unroll
        for (int h = 0; h < 2; ++h) {
            const int row = wm * 64 + mt * 16 + (lane >> 2) + h * 8;
            const int g = __ldg(gid + mBase + row);
            const float* qrow = qeff + (size_t)g * PD_ + nBase;
            float s = 0.f;
#pragma unroll
            for (int nt = 0; nt < 8; ++nt) {
                const int nn = n0 + nt * 8;
                float2 q2 = *reinterpret_cast<const float2*>(qrow + nn);
                float2 w2 = *reinterpret_cast<const float2*>(wv + nBase + nn);
                float x0 = tanhf(c[mt][nt][h * 2 + 0] + q2.x);
                float x1 = tanhf(c[mt][nt][h * 2 + 1] + q2.y);
                s = fmaf(x0, w2.x, s);
                s = fmaf(x1, w2.y, s);
            }
            s += __shfl_xor_sync(0xffffffffu, s, 1);
            s += __shfl_xor_sync(0xffffffffu, s, 2);
            if ((lane & 3) == 0) atomicAdd(&s_sm[row], s);
        }
    }
    __syncthreads();
    atomicAdd(&sOut[mBase + tid], s_sm[tid]);
}

// ---------------- prep kernels ----------------
__global__ void k_zero(float* sn, float* se, float* qn, float* qe) {
    int i = blockIdx.x * blockDim.x + threadIdx.x;
    if (i < TN_) sn[i] = 0.f;
    if (i < TE_) se[i] = 0.f;
    if (i < B_ * PD_) { qn[i] = 0.f; qe[i] = 0.f; }
}

// Wt[p][k] = bf16(W[k][p])  (512x512), grid.z selects node/edge
__global__ void k_transpose(const float* __restrict__ Wn, const float* __restrict__ We,
                            __nv_bfloat16* __restrict__ WtN, __nv_bfloat16* __restrict__ WtE) {
    const float* W = blockIdx.z ? We : Wn;
    __nv_bfloat16* Wt = blockIdx.z ? WtE : WtN;
    __shared__ float tile[32][33];
    int x = blockIdx.x * 32 + threadIdx.x;   // p
    int y = blockIdx.y * 32 + threadIdx.y;   // k
#pragma unroll
    for (int j = 0; j < 32; j += 8)
        tile[threadIdx.y + j][threadIdx.x] = W[(y + j) * 512 + x];
    __syncthreads();
    int xo = blockIdx.y * 32 + threadIdx.x;  // k
    int yo = blockIdx.x * 32 + threadIdx.y;  // p
#pragma unroll
    for (int j = 0; j < 32; j += 8)
        Wt[(yo + j) * 512 + xo] = __float2bfloat16(tile[threadIdx.x][threadIdx.y + j]);
}

// split-k qproj, grid (B_, 8, 2): z selects node/edge weights.
__global__ void __launch_bounds__(256) k_qproj(
    const float* __restrict__ q,
    const float* __restrict__ WqN, const float* __restrict__ bqN, const float* __restrict__ bhN,
    const float* __restrict__ WqE, const float* __restrict__ bqE, const float* __restrict__ bhE,
    float* __restrict__ outN, float* __restrict__ outE) {
    const float* Wq = blockIdx.z ? WqE : WqN;
    const float* bq = blockIdx.z ? bqE : bqN;
    const float* bh = blockIdx.z ? bhE : bhN;
    float* out = blockIdx.z ? outE : outN;
    __shared__ float qs[96];
    const int b = blockIdx.x, ks = blockIdx.y;
    const int k0 = ks * 96;
    const int t = threadIdx.x;
    if (t < 96) qs[t] = q[b * QD_ + k0 + t];
    __syncthreads();
    const int p0 = t, p1 = t + 256;
    float a0 = 0.f, a1 = 0.f;
#pragma unroll 4
    for (int k = 0; k < 96; ++k) {
        const float* wrow = Wq + (size_t)(k0 + k) * 512;
        a0 = fmaf(qs[k], __ldg(wrow + p0), a0);
        a1 = fmaf(qs[k], __ldg(wrow + p1), a1);
    }
    if (ks == 0) {
        a0 += __ldg(bq + p0) + __ldg(bh + p0);
        a1 += __ldg(bq + p1) + __ldg(bh + p1);
    }
    atomicAdd(out + b * 512 + p0, a0);
    atomicAdd(out + b * 512 + p1, a1);
}

// ---------------- fused per-graph softmax (gid sorted -> contiguous segments) ----
__global__ void __launch_bounds__(256) k_soft(
    const float* __restrict__ sn, const float* __restrict__ se,
    const int* __restrict__ gidN, const int* __restrict__ gidE,
    float* __restrict__ out) {
    const bool isNode = blockIdx.x < 64;
    const int g = isNode ? blockIdx.x : blockIdx.x - 64;
    const float* s  = isNode ? sn : se;
    const int* gid  = isNode ? gidN : gidE;
    const int n     = isNode ? TN_ : TE_;
    float* o        = out + (isNode ? 0 : TN_);

    const int t = threadIdx.x;
    __shared__ float red[256];
    __shared__ int bounds[2];

    if (t < 2) {
        int target = g + t;
        int lo = 0, hi = n;
        while (lo < hi) {
            int mid = (lo + hi) >> 1;
            if (__ldg(gid + mid) < target) lo = mid + 1; else hi = mid;
        }
        bounds[t] = lo;
    }
    __syncthreads();
    const int lo = bounds[0], hi = bounds[1];

    float m = -3.0e38f;
    for (int i = lo + t; i < hi; i += 256) m = fmaxf(m, __ldg(s + i));
    red[t] = m;
    __syncthreads();
#pragma unroll
    for (int st = 128; st >= 1; st >>= 1) {
        if (t < st) red[t] = fmaxf(red[t], red[t + st]);
        __syncthreads();
    }
    m = red[0];
    __syncthreads();

    float z = 0.f;
    for (int i = lo + t; i < hi; i += 256) z += expf(__ldg(s + i) - m);
    red[t] = z;
    __syncthreads();
#pragma unroll
    for (int st = 128; st >= 1; st >>= 1) {
        if (t < st) red[t] += red[t + st];
        __syncthreads();
    }
    const float rz = 1.f / red[0];

    for (int i = lo + t; i < hi; i += 256)
        o[i] = expf(__ldg(s + i) - m) * rz;
}

// ---------------- launch ----------------
extern "C" void kernel_launch(void* const* d_in, const int* in_sizes, int n_in,
                              void* d_out, int out_size) {
    const float* question = (const float*)d_in[0];
    const float* nodes    = (const float*)d_in[1];
    const float* edges    = (const float*)d_in[2];
    const float* W_nq     = (const float*)d_in[3];
    const float* b_nq     = (const float*)d_in[4];
    const float* W_n      = (const float*)d_in[5];
    const float* b_n      = (const float*)d_in[6];
    const float* w_nv     = (const float*)d_in[7];
    // d_in[8] = b_nv — softmax shift-invariant, unused
    const float* W_eq     = (const float*)d_in[9];
    const float* b_eq     = (const float*)d_in[10];
    const float* W_e      = (const float*)d_in[11];
    const float* b_e      = (const float*)d_in[12];
    const float* w_ev     = (const float*)d_in[13];
    // d_in[14] = b_ev — unused
    const int* node_gid   = (const int*)d_in[15];
    const int* edge_gid   = (const int*)d_in[16];
    float* out = (float*)d_out;

    float *qn, *qe, *sn, *se;
    __nv_bfloat16 *wtn, *wte;
    cudaGetSymbolAddress((void**)&qn,  g_qn);
    cudaGetSymbolAddress((void**)&qe,  g_qe);
    cudaGetSymbolAddress((void**)&wtn, g_wtn);
    cudaGetSymbolAddress((void**)&wte, g_wte);
    cudaGetSymbolAddress((void**)&sn,  g_sn);
    cudaGetSymbolAddress((void**)&se,  g_se);

    cudaFuncSetAttribute(k_main, cudaFuncAttributeMaxDynamicSharedMemorySize, SMEM_BYTES);

    k_zero<<<TE_ / 512, 512>>>(sn, se, qn, qe);
    k_transpose<<<dim3(16, 16, 2), dim3(32, 8)>>>(W_n, W_e, wtn, wte);
    k_qproj<<<dim3(B_, 8, 2), 256>>>(question,
                                     W_nq, b_nq, b_n,
                                     W_eq, b_eq, b_e, qn, qe);

    k_main<<<dim3(4, NYN + TE_ / 256), 256, SMEM_BYTES>>>(
        nodes, edges, node_gid, edge_gid, wtn, wte, qn, qe, w_nv, w_ev, sn, se);

    k_soft<<<128, 256>>>(sn, se, node_gid, edge_gid, out);
}